// round 5
// baseline (speedup 1.0000x reference)
#include <cuda_runtime.h>

// Problem constants
#define T_STEPS 500
#define BATCH   1024
#define NDIM    256
#define ALPHA_F 0.995f   // 1 - 0.05/10
#define VTH_F   1.0f

// Producer/consumer chunking
#define CHUNK_T     20
#define N_CHUNKS    (T_STEPS / CHUNK_T)     // 25
#define ROWS_CHUNK  (CHUNK_T * BATCH)       // 20480 rows per chunk
#define TPB         256
#define C_BLOCKS    4                       // consumer blocks (first in grid)
#define P_BLOCKS    512                     // producer blocks
#define P_WARPS     (P_BLOCKS * (TPB / 32)) // 4096 producer warps
#define ROWS_PW     (ROWS_CHUNK / P_WARPS)  // 5 rows / warp / chunk

// Scratch: per-(t,b) input currents (2 MB, L2-resident) + sync flags
__device__ float    g_s[T_STEPS * BATCH];
__device__ unsigned g_flag[N_CHUNKS];   // #producer WARPS done with chunk c
__device__ unsigned g_done[N_CHUNKS];   // #consumer blocks done (self-clean)

__device__ __forceinline__ unsigned ld_acquire_gpu(const unsigned* p) {
    unsigned v;
    asm volatile("ld.acquire.gpu.u32 %0, [%1];" : "=r"(v) : "l"(p) : "memory");
    return v;
}

// release-ordered, no-return add: orders this thread's prior stores before the add
__device__ __forceinline__ void red_release_gpu_add(unsigned* p, unsigned v) {
    asm volatile("red.release.gpu.global.add.u32 [%0], %1;" :: "l"(p), "r"(v) : "memory");
}

__device__ __forceinline__ float4 ldcs_f4(const float4* p) {
    float4 v;
    asm volatile("ld.global.cs.v4.f32 {%0,%1,%2,%3}, [%4];"
                 : "=f"(v.x), "=f"(v.y), "=f"(v.z), "=f"(v.w) : "l"(p));
    return v;
}

__global__ void __launch_bounds__(TPB) lif_fused_kernel(
    const float* __restrict__ x,      // [T, B, N]
    const float* __restrict__ w,      // [N]
    float* __restrict__ out)          // [2, T, B]  (v then z)
{
    const int tid = threadIdx.x;

    if (blockIdx.x >= C_BLOCKS) {
        // ================= PRODUCER (barrier-free) =================
        // Each warp owns 5 consecutive rows per chunk; after storing them it
        // fires one release-RED on the chunk flag and streams straight into
        // the next chunk's loads. No __syncthreads, no __threadfence.
        const int pb   = blockIdx.x - C_BLOCKS;        // 0..511
        const int warp = tid >> 5;
        const int lane = tid & 31;
        const int gw   = pb * (TPB / 32) + warp;       // 0..4095

        const float4* wv = reinterpret_cast<const float4*>(w);
        const float4 w0 = wv[lane];
        const float4 w1 = wv[lane + 32];

        #pragma unroll 1
        for (int c = 0; c < N_CHUNKS; ++c) {
            const long long rbase = (long long)c * ROWS_CHUNK
                                  + (long long)gw * ROWS_PW;

            float4 a[2 * ROWS_PW];
            #pragma unroll
            for (int i = 0; i < ROWS_PW; ++i) {
                const float4* xr =
                    reinterpret_cast<const float4*>(x + (rbase + i) * NDIM);
                a[2 * i]     = ldcs_f4(xr + lane);        // streaming loads
                a[2 * i + 1] = ldcs_f4(xr + lane + 32);
            }

            float acc[ROWS_PW];
            #pragma unroll
            for (int i = 0; i < ROWS_PW; ++i) {
                const float4 p0 = a[2 * i], p1 = a[2 * i + 1];
                acc[i] = p0.x * w0.x + p0.y * w0.y + p0.z * w0.z + p0.w * w0.w
                       + p1.x * w1.x + p1.y * w1.y + p1.z * w1.z + p1.w * w1.w;
            }
            // interleave the 5 reduce trees level-by-level for ILP
            #pragma unroll
            for (int off = 16; off > 0; off >>= 1) {
                #pragma unroll
                for (int i = 0; i < ROWS_PW; ++i)
                    acc[i] += __shfl_xor_sync(0xffffffffu, acc[i], off);
            }
            if (lane == 0) {
                #pragma unroll
                for (int i = 0; i < ROWS_PW; ++i)
                    g_s[rbase + i] = acc[i];
                // release: publishes this thread's g_s stores, counts one warp
                red_release_gpu_add(&g_flag[c], 1u);
            }
        }
    } else {
        // ================= CONSUMER =================
        const int b = blockIdx.x * TPB + tid;   // 0..1023
        float* __restrict__ vout = out;                               // [T, B]
        float* __restrict__ zout = out + (long long)T_STEPS * BATCH;  // [T, B]

        float v = 0.0f, z = 0.0f;

        #pragma unroll 1
        for (int c = 0; c < N_CHUNKS; ++c) {
            if (tid == 0) {
                while (ld_acquire_gpu(&g_flag[c]) < P_WARPS) { }
            }
            __syncthreads();   // order all threads after the acquire

            const int tbase = c * CHUNK_T;

            float s[CHUNK_T];
            #pragma unroll
            for (int i = 0; i < CHUNK_T; ++i)
                s[i] = g_s[(tbase + i) * BATCH + b];

            #pragma unroll
            for (int i = 0; i < CHUNK_T; ++i) {
                v = ALPHA_F * v + s[i] - z;
                z = (v > VTH_F) ? 1.0f : 0.0f;
                const int t = tbase + i;
                vout[(long long)t * BATCH + b] = v;
                zout[(long long)t * BATCH + b] = z;
            }

            __syncthreads();
            // self-clean flags for next graph replay: last consumer block resets
            if (tid == 0) {
                if (atomicAdd(&g_done[c], 1u) == C_BLOCKS - 1) {
                    g_flag[c] = 0;
                    g_done[c] = 0;
                }
            }
        }
    }
}

// ---------------------------------------------------------------------------
extern "C" void kernel_launch(void* const* d_in, const int* in_sizes, int n_in,
                              void* d_out, int out_size)
{
    const float* x = (const float*)d_in[0];   // [T, B, N] fp32
    const float* w = (const float*)d_in[1];   // [N] fp32
    float* out = (float*)d_out;               // [2, T, B] fp32

    lif_fused_kernel<<<P_BLOCKS + C_BLOCKS, TPB>>>(x, w, out);
}

// round 6
// speedup vs baseline: 1.2482x; 1.2482x over previous
#include <cuda_runtime.h>

// Problem constants
#define T_STEPS 500
#define BATCH   1024
#define NDIM    256
#define ALPHA_F 0.995f   // 1 - 0.05/10
#define VTH_F   1.0f

// Chunking (producer ordering / consumer batching only — NO sync objects)
#define CHUNK_T     20
#define N_CHUNKS    (T_STEPS / CHUNK_T)     // 25
#define ROWS_CHUNK  (CHUNK_T * BATCH)       // 20480
#define TPB         256
#define C_BLOCKS    4                       // consumer blocks (first in grid)
#define P_BLOCKS    512                     // producer blocks
#define P_WARPS     (P_BLOCKS * (TPB / 32)) // 4096
#define ROWS_PW     (ROWS_CHUNK / P_WARPS)  // 5 rows / warp / chunk

#define SENTINEL 0xFFFFFFFFu   // NaN bit pattern unreachable by finite FMA chains

// Scratch: per-(t,b) input currents (2 MB, L2-resident).
// The VALUE doubles as the ready flag: init kernel poisons with SENTINEL,
// producers overwrite, consumers spin until bits != SENTINEL.
__device__ float g_s[T_STEPS * BATCH];

__device__ __forceinline__ unsigned ld_volatile_u32(const float* p) {
    unsigned v;
    asm volatile("ld.volatile.global.u32 %0, [%1];" : "=r"(v) : "l"(p) : "memory");
    return v;
}

// ---------------------------------------------------------------------------
// Kernel 0: poison g_s with the sentinel (runs every graph replay).
// 512000 words = 128000 uint4 stores; 500 blocks x 256 threads.
// ---------------------------------------------------------------------------
__global__ void __launch_bounds__(TPB) lif_init_kernel()
{
    uint4* p = reinterpret_cast<uint4*>(g_s);
    const int i = blockIdx.x * TPB + threadIdx.x;
    p[i] = make_uint4(SENTINEL, SENTINEL, SENTINEL, SENTINEL);
}

// ---------------------------------------------------------------------------
// Kernel 1: fused producer/consumer, zero producer-side synchronization.
// ---------------------------------------------------------------------------
__global__ void __launch_bounds__(TPB) lif_fused_kernel(
    const float* __restrict__ x,      // [T, B, N]
    const float* __restrict__ w,      // [N]
    float* __restrict__ out)          // [2, T, B]  (v then z)
{
    const int tid = threadIdx.x;

    if (blockIdx.x >= C_BLOCKS) {
        // ================= PRODUCER =================
        // Identical instruction mix to the standalone roofline GEMV:
        // 10 independent float4 loads, 5 interleaved shfl-reduce trees,
        // plain stores. No barriers, no fences, no atomics.
        const int pb   = blockIdx.x - C_BLOCKS;        // 0..511
        const int warp = tid >> 5;
        const int lane = tid & 31;
        const int gw   = pb * (TPB / 32) + warp;       // 0..4095

        const float4* wv = reinterpret_cast<const float4*>(w);
        const float4 w0 = wv[lane];
        const float4 w1 = wv[lane + 32];

        #pragma unroll 1
        for (int c = 0; c < N_CHUNKS; ++c) {
            const long long rbase = (long long)c * ROWS_CHUNK
                                  + (long long)gw * ROWS_PW;

            float4 a[2 * ROWS_PW];
            #pragma unroll
            for (int i = 0; i < ROWS_PW; ++i) {
                const float4* xr =
                    reinterpret_cast<const float4*>(x + (rbase + i) * NDIM);
                a[2 * i]     = xr[lane];
                a[2 * i + 1] = xr[lane + 32];
            }

            float acc[ROWS_PW];
            #pragma unroll
            for (int i = 0; i < ROWS_PW; ++i) {
                const float4 p0 = a[2 * i], p1 = a[2 * i + 1];
                acc[i] = p0.x * w0.x + p0.y * w0.y + p0.z * w0.z + p0.w * w0.w
                       + p1.x * w1.x + p1.y * w1.y + p1.z * w1.z + p1.w * w1.w;
            }
            #pragma unroll
            for (int off = 16; off > 0; off >>= 1) {
                #pragma unroll
                for (int i = 0; i < ROWS_PW; ++i)
                    acc[i] += __shfl_xor_sync(0xffffffffu, acc[i], off);
            }
            if (lane == 0) {
                #pragma unroll
                for (int i = 0; i < ROWS_PW; ++i)
                    g_s[rbase + i] = acc[i];   // plain store; value == flag
            }
        }
    } else {
        // ================= CONSUMER =================
        const int b = blockIdx.x * TPB + tid;   // 0..1023
        float* __restrict__ vout = out;                               // [T, B]
        float* __restrict__ zout = out + (long long)T_STEPS * BATCH;  // [T, B]

        float v = 0.0f, z = 0.0f;

        #pragma unroll 1
        for (int c = 0; c < N_CHUNKS; ++c) {
            const int tbase = c * CHUNK_T;

            // batch-issue 20 L1-bypassing loads, then verify / spin per word
            unsigned bits[CHUNK_T];
            #pragma unroll
            for (int i = 0; i < CHUNK_T; ++i)
                bits[i] = ld_volatile_u32(&g_s[(tbase + i) * BATCH + b]);

            #pragma unroll
            for (int i = 0; i < CHUNK_T; ++i) {
                while (bits[i] == SENTINEL)
                    bits[i] = ld_volatile_u32(&g_s[(tbase + i) * BATCH + b]);
            }

            #pragma unroll
            for (int i = 0; i < CHUNK_T; ++i) {
                const float s = __uint_as_float(bits[i]);
                v = ALPHA_F * v + s - z;
                z = (v > VTH_F) ? 1.0f : 0.0f;
                const int t = tbase + i;
                vout[(long long)t * BATCH + b] = v;
                zout[(long long)t * BATCH + b] = z;
            }
        }
    }
}

// ---------------------------------------------------------------------------
extern "C" void kernel_launch(void* const* d_in, const int* in_sizes, int n_in,
                              void* d_out, int out_size)
{
    const float* x = (const float*)d_in[0];   // [T, B, N] fp32
    const float* w = (const float*)d_in[1];   // [N] fp32
    float* out = (float*)d_out;               // [2, T, B] fp32

    lif_init_kernel<<<(T_STEPS * BATCH) / (TPB * 4), TPB>>>();
    lif_fused_kernel<<<P_BLOCKS + C_BLOCKS, TPB>>>(x, w, out);
}

// round 7
// speedup vs baseline: 1.5714x; 1.2589x over previous
#include <cuda_runtime.h>

// Problem constants
#define T_STEPS 500
#define BATCH   1024
#define NDIM    256
#define ALPHA_F 0.995f   // 1 - 0.05/10
#define VTH_F   1.0f

// Chunking
#define CHUNK_T      20
#define N_CHUNKS     (T_STEPS / CHUNK_T)      // 25
#define ROWS_CHUNK   (CHUNK_T * BATCH)        // 20480 rows / chunk
#define TPB          256
#define C_BLOCKS     4                        // consumer blocks (first in grid)
#define BPC          512                      // producer blocks per chunk
#define ROWS_PB      (ROWS_CHUNK / BPC)       // 40 rows / block
#define ROWS_PW      (ROWS_PB / (TPB / 32))   // 5 rows / warp
#define P_BLOCKS     (N_CHUNKS * BPC)         // 12800 one-shot producer blocks

// Scratch: per-(t,b) input currents (2 MB, L2-resident) + sync flags
__device__ float    g_s[T_STEPS * BATCH];
__device__ unsigned g_flag[N_CHUNKS];   // #producer blocks done with chunk c
__device__ unsigned g_done[N_CHUNKS];   // #consumer blocks done (self-clean)

__device__ __forceinline__ unsigned ld_acquire_gpu(const unsigned* p) {
    unsigned v;
    asm volatile("ld.acquire.gpu.u32 %0, [%1];" : "=r"(v) : "l"(p) : "memory");
    return v;
}

__global__ void __launch_bounds__(TPB) lif_fused_kernel(
    const float* __restrict__ x,      // [T, B, N]
    const float* __restrict__ w,      // [N]
    float* __restrict__ out)          // [2, T, B]  (v then z)
{
    const int tid = threadIdx.x;

    if (blockIdx.x >= C_BLOCKS) {
        // ========== PRODUCER (one-shot: 40 rows of one chunk) ==========
        // Non-persistent blocks -> wave scheduler load-balances SMs
        // automatically (persistent R4 lost ~15% to static imbalance).
        const int pb   = blockIdx.x - C_BLOCKS;   // 0..12799, chunk-major
        const int c    = pb >> 9;                 // pb / 512 : chunk id
        const int slab = pb & 511;                // block-within-chunk
        const int warp = tid >> 5;
        const int lane = tid & 31;

        const long long rbase = (long long)c * ROWS_CHUNK
                              + slab * ROWS_PB + warp * ROWS_PW;

        const float4* wv = reinterpret_cast<const float4*>(w);
        const float4 w0 = wv[lane];
        const float4 w1 = wv[lane + 32];

        float4 a[2 * ROWS_PW];
        #pragma unroll
        for (int i = 0; i < ROWS_PW; ++i) {
            const float4* xr =
                reinterpret_cast<const float4*>(x + (rbase + i) * NDIM);
            a[2 * i]     = xr[lane];
            a[2 * i + 1] = xr[lane + 32];
        }

        float acc[ROWS_PW];
        #pragma unroll
        for (int i = 0; i < ROWS_PW; ++i) {
            const float4 p0 = a[2 * i], p1 = a[2 * i + 1];
            acc[i] = p0.x * w0.x + p0.y * w0.y + p0.z * w0.z + p0.w * w0.w
                   + p1.x * w1.x + p1.y * w1.y + p1.z * w1.z + p1.w * w1.w;
        }
        #pragma unroll
        for (int off = 16; off > 0; off >>= 1) {
            #pragma unroll
            for (int i = 0; i < ROWS_PW; ++i)
                acc[i] += __shfl_xor_sync(0xffffffffu, acc[i], off);
        }
        if (lane == 0) {
            #pragma unroll
            for (int i = 0; i < ROWS_PW; ++i)
                g_s[rbase + i] = acc[i];
        }

        __syncthreads();                  // block's g_s stores complete
        if (tid == 0) {
            __threadfence();              // publish before counting
            atomicAdd(&g_flag[c], 1u);
        }
        // block exits; scheduler refills the SM slot with a fresh block
    } else {
        // ================= CONSUMER (persistent, 25 chunks) =================
        const int b = blockIdx.x * TPB + tid;   // 0..1023
        float* __restrict__ vout = out;                               // [T, B]
        float* __restrict__ zout = out + (long long)T_STEPS * BATCH;  // [T, B]

        float v = 0.0f, z = 0.0f;

        #pragma unroll 1
        for (int c = 0; c < N_CHUNKS; ++c) {
            if (tid == 0) {
                while (ld_acquire_gpu(&g_flag[c]) < BPC) { }
            }
            __syncthreads();   // order all threads after the acquire

            const int tbase = c * CHUNK_T;

            float s[CHUNK_T];
            #pragma unroll
            for (int i = 0; i < CHUNK_T; ++i)
                s[i] = g_s[(tbase + i) * BATCH + b];

            #pragma unroll
            for (int i = 0; i < CHUNK_T; ++i) {
                v = ALPHA_F * v + s[i] - z;
                z = (v > VTH_F) ? 1.0f : 0.0f;
                const int t = tbase + i;
                vout[(long long)t * BATCH + b] = v;
                zout[(long long)t * BATCH + b] = z;
            }

            __syncthreads();
            // self-clean flags for next graph replay: last consumer block resets
            if (tid == 0) {
                if (atomicAdd(&g_done[c], 1u) == C_BLOCKS - 1) {
                    g_flag[c] = 0;
                    g_done[c] = 0;
                }
            }
        }
    }
}

// ---------------------------------------------------------------------------
extern "C" void kernel_launch(void* const* d_in, const int* in_sizes, int n_in,
                              void* d_out, int out_size)
{
    const float* x = (const float*)d_in[0];   // [T, B, N] fp32
    const float* w = (const float*)d_in[1];   // [N] fp32
    float* out = (float*)d_out;               // [2, T, B] fp32

    lif_fused_kernel<<<C_BLOCKS + P_BLOCKS, TPB>>>(x, w, out);
}